// round 16
// baseline (speedup 1.0000x reference)
#include <cuda_runtime.h>
#include <cuda_bf16.h>
#include <math.h>
#include <cstdint>

// Problem constants
#define Bsz   4
#define Ssz   2048
#define Dsz   1024
#define Hsz   16
#define DKsz  64
#define DFFsz 4096
#define Msz   (Bsz*Ssz)   // 8192 rows

typedef __nv_bfloat16 bf16;

// ---------------- scratch ----------------
__device__ float g_tmp [(size_t)Msz*Dsz];
__device__ float g_x1  [(size_t)Msz*Dsz];
__device__ float g_gate[(size_t)Msz*Hsz];

__device__ bf16 g_xh [(size_t)Msz*Dsz],   g_xl [(size_t)Msz*Dsz];
__device__ bf16 g_qh [(size_t)Msz*Dsz];
__device__ bf16 g_kh [(size_t)Msz*Dsz];
__device__ bf16 g_vh [(size_t)Msz*Dsz];
__device__ bf16 g_ctxh[(size_t)Msz*Dsz];
__device__ bf16 g_x1h[(size_t)Msz*Dsz],   g_x1l[(size_t)Msz*Dsz];
__device__ bf16 g_ffh[(size_t)Msz*DFFsz], g_ffl[(size_t)Msz*DFFsz];
__device__ bf16 g_wqh[(size_t)Dsz*Dsz];
__device__ bf16 g_wkh[(size_t)Dsz*Dsz];
__device__ bf16 g_wvh[(size_t)Dsz*Dsz];
__device__ bf16 g_woh[(size_t)Dsz*Dsz];
__device__ bf16 g_w1h[(size_t)Dsz*DFFsz], g_w1l[(size_t)Dsz*DFFsz];
__device__ bf16 g_w2h[(size_t)DFFsz*Dsz];

// ---------------- small helpers ----------------
__device__ __forceinline__ void cp16(uint32_t dst, const void* src) {
    asm volatile("cp.async.ca.shared.global [%0], [%1], 16;\n" :: "r"(dst), "l"(src));
}
__device__ __forceinline__ void cp_commit() {
    asm volatile("cp.async.commit_group;\n");
}
__device__ __forceinline__ void cp_wait0() {
    asm volatile("cp.async.wait_group 0;\n");
}
__device__ __forceinline__ void cp_wait1() {
    asm volatile("cp.async.wait_group 1;\n");
}
__device__ __forceinline__ void cp_wait2() {
    asm volatile("cp.async.wait_group 2;\n");
}
__device__ __forceinline__ void ldsm4(uint32_t* r, uint32_t addr) {
    asm volatile("ldmatrix.sync.aligned.m8n8.x4.shared.b16 {%0,%1,%2,%3}, [%4];"
                 : "=r"(r[0]), "=r"(r[1]), "=r"(r[2]), "=r"(r[3]) : "r"(addr));
}
__device__ __forceinline__ void ldsm4t(uint32_t& r0, uint32_t& r1,
                                       uint32_t& r2, uint32_t& r3, uint32_t addr) {
    asm volatile("ldmatrix.sync.aligned.m8n8.x4.trans.shared.b16 {%0,%1,%2,%3}, [%4];"
                 : "=r"(r0), "=r"(r1), "=r"(r2), "=r"(r3) : "r"(addr));
}
__device__ __forceinline__ void mma16816(float* ac, const uint32_t* a,
                                         uint32_t b0, uint32_t b1) {
    asm volatile(
        "mma.sync.aligned.m16n8k16.row.col.f32.bf16.bf16.f32 "
        "{%0,%1,%2,%3},{%4,%5,%6,%7},{%8,%9},{%0,%1,%2,%3};"
        : "+f"(ac[0]), "+f"(ac[1]), "+f"(ac[2]), "+f"(ac[3])
        : "r"(a[0]), "r"(a[1]), "r"(a[2]), "r"(a[3]), "r"(b0), "r"(b1));
}
__device__ __forceinline__ void pack_pair(float a, float b, uint32_t& hi, uint32_t& lo) {
    bf16 ha = __float2bfloat16(a), hb = __float2bfloat16(b);
    bf16 la = __float2bfloat16(a - __bfloat162float(ha));
    bf16 lb = __float2bfloat16(b - __bfloat162float(hb));
    __nv_bfloat162 th = __halves2bfloat162(ha, hb);
    __nv_bfloat162 tl = __halves2bfloat162(la, lb);
    hi = *(uint32_t*)&th; lo = *(uint32_t*)&tl;
}
__device__ __forceinline__ uint32_t pack_hi(float a, float b) {
    __nv_bfloat162 th = __halves2bfloat162(__float2bfloat16(a), __float2bfloat16(b));
    return *(uint32_t*)&th;
}

// ---------------- splits (2 float4 per thread) ----------------
__global__ __launch_bounds__(256)
void split_x_kernel(const float* __restrict__ in, bf16* __restrict__ hi,
                    bf16* __restrict__ lo)
{
    size_t base = (size_t)blockIdx.x * 512 + threadIdx.x;
    #pragma unroll
    for (int k = 0; k < 2; k++) {
        size_t i = base + k * 256;
        float4 v = ((const float4*)in)[i];
        uint32_t h0, l0, h1, l1;
        pack_pair(v.x, v.y, h0, l0);
        pack_pair(v.z, v.w, h1, l1);
        ((uint32_t*)hi)[2*i] = h0; ((uint32_t*)hi)[2*i+1] = h1;
        ((uint32_t*)lo)[2*i] = l0; ((uint32_t*)lo)[2*i+1] = l1;
    }
}

struct SplitWArgs {
    const float* src[6];
    bf16* hi[6];
    bf16* lo[6];      // nullptr -> hi only
};
__global__ __launch_bounds__(256)
void split_w_kernel(SplitWArgs a)
{
    int bid = blockIdx.x;
    int seg, base;
    if      (bid < 512)   { seg = 0; base = 0; }
    else if (bid < 1024)  { seg = 1; base = 512; }
    else if (bid < 1536)  { seg = 2; base = 1024; }
    else if (bid < 2048)  { seg = 3; base = 1536; }
    else if (bid < 4096)  { seg = 4; base = 2048; }
    else                  { seg = 5; base = 4096; }
    const float* src = a.src[seg];
    bf16* hi = a.hi[seg];
    bf16* lo = a.lo[seg];
    size_t b0 = (size_t)(bid - base) * 512 + threadIdx.x;
    #pragma unroll
    for (int k = 0; k < 2; k++) {
        size_t i = b0 + k * 256;
        float4 v = ((const float4*)src)[i];
        uint32_t h0, l0, h1, l1;
        pack_pair(v.x, v.y, h0, l0);
        pack_pair(v.z, v.w, h1, l1);
        ((uint32_t*)hi)[2*i] = h0; ((uint32_t*)hi)[2*i+1] = h1;
        if (lo) {
            ((uint32_t*)lo)[2*i] = l0; ((uint32_t*)lo)[2*i+1] = l1;
        }
    }
}

// ---------------- 1-term bf16 GEMM: BN=128, BK=32, 3-stage ------
#define AP2 40              // 32 + 8 pad (80B stride)
#define WPAD1 136           // 128 + 8 pad
#define G1A (128*AP2*2)     // 10240 B per A stage
#define G1W (32*WPAD1*2)    // 8704 B per W stage
#define GSMEM1 (3*(G1A + G1W))   // 56832

__device__ __forceinline__
void gemm1_core(const bf16* __restrict__ Ah,
                const bf16* __restrict__ Wh,
                const float* __restrict__ bias, float* __restrict__ C,
                bf16* __restrict__ Ch,
                int N, int K, int mode, int row0, int col0)
{
    extern __shared__ __align__(16) char gdsm[];
    const uint32_t aAh = (uint32_t)__cvta_generic_to_shared(gdsm);
    const uint32_t aWh = aAh + 3*G1A;

    const int tid = threadIdx.x;

    // A: row tid>>1, elems (tid&1)*16 + {0,8}
    const int arow = tid >> 1;
    const int ae0 = (tid & 1) * 16;
    const char* pAh = (const char*)(Ah + (size_t)(row0 + arow) * K + ae0);
    const uint32_t dA0 = (uint32_t)((arow*AP2 + ae0) * 2);

    // W: krows tid>>4 + {0,16}, col (tid&15)*8
    const int wk0 = tid >> 4;
    const int wcol = (tid & 15) * 8;
    const char* pWh = (const char*)(Wh + (size_t)wk0 * N + col0 + wcol);
    const uint32_t dW0 = (uint32_t)((wk0*WPAD1 + wcol) * 2);
    const uint32_t dW16 = (uint32_t)(16*WPAD1*2);
    const size_t  gW16 = (size_t)16 * N * 2;

    float acc[4][4][4];
    #pragma unroll
    for (int i = 0; i < 4; i++)
        #pragma unroll
        for (int j = 0; j < 4; j++)
            #pragma unroll
            for (int t = 0; t < 4; t++) acc[i][j][t] = 0.0f;

    const int wid = tid >> 5, lane = tid & 31;
    const int wm = wid & 1;
    const int wn = wid >> 1;
    const int lrow = lane & 15, lk = (lane >> 4) * 8;
    const uint32_t offA0 = (uint32_t)(((wm*64 + lrow) * AP2 + lk) * 2);
    const uint32_t offB0 = (uint32_t)(((lane & 15) * WPAD1 + wn*32 + (lane>>4)*8) * 2);

    const int nit = K / 32;

    auto load_stage = [&](int st, int it2) {
        size_t ka = (size_t)it2 * 32 * 2;
        size_t kw = (size_t)it2 * 32 * (size_t)N * 2;
        uint32_t sa = aAh + (uint32_t)(st*G1A);
        cp16(sa + dA0, pAh + ka);
        cp16(sa + dA0 + 16, pAh + ka + 16);
        uint32_t sw = aWh + (uint32_t)(st*G1W);
        cp16(sw + dW0, pWh + kw);
        cp16(sw + dW0 + dW16, pWh + kw + gW16);
        cp_commit();
    };

    load_stage(0, 0);
    load_stage(1, 1);

    for (int it = 0; it < nit; ++it) {
        int rem = nit - 1 - it;
        if (rem >= 1) cp_wait1(); else cp_wait0();
        __syncthreads();
        if (it + 2 < nit)
            load_stage((it + 2) % 3, it + 2);
        const uint32_t s = (uint32_t)(it % 3);

        #pragma unroll
        for (int kh = 0; kh < 2; kh++) {
            const uint32_t kaoff = (uint32_t)(kh * 16 * 2);
            const uint32_t kwoff = (uint32_t)(kh * 16 * WPAD1 * 2);

            uint32_t afh[4][4];
            #pragma unroll
            for (int mi = 0; mi < 4; mi++)
                ldsm4(afh[mi], aAh + s*G1A + offA0 + kaoff + (uint32_t)(mi*16*AP2*2));

            uint32_t bfr[4][2];
            #pragma unroll
            for (int ng = 0; ng < 2; ng++)
                ldsm4t(bfr[2*ng][0], bfr[2*ng][1], bfr[2*ng+1][0], bfr[2*ng+1][1],
                       aWh + (uint32_t)(s*G1W) + offB0 + kwoff + (uint32_t)(ng*16*2));

            #pragma unroll
            for (int mi = 0; mi < 4; mi++)
                #pragma unroll
                for (int ni = 0; ni < 4; ni++)
                    mma16816(acc[mi][ni], afh[mi], bfr[ni][0], bfr[ni][1]);
        }
    }

    #pragma unroll
    for (int mi = 0; mi < 4; mi++) {
        #pragma unroll
        for (int ni = 0; ni < 4; ni++) {
            int c = col0 + wn*32 + ni*8 + (lane & 3)*2;
            float bx = bias[c], by = bias[c + 1];
            #pragma unroll
            for (int rh = 0; rh < 2; rh++) {
                size_t r = (size_t)(row0 + wm*64 + mi*16 + (lane >> 2) + rh*8);
                float v0 = acc[mi][ni][2*rh]     + bx;
                float v1 = acc[mi][ni][2*rh + 1] + by;
                if (mode & 2) {
                    float2 o; o.x = v0; o.y = v1;
                    *(float2*)&C[r * N + c] = o;
                }
                if (mode & 8) {
                    *(uint32_t*)&Ch[r * N + c] = pack_hi(v0, v1);
                }
            }
        }
    }
}

__global__ __launch_bounds__(256)
void gemm_bf16x1_kernel(const bf16* __restrict__ Ah,
                        const bf16* __restrict__ Wh,
                        const float* __restrict__ bias, float* __restrict__ C,
                        bf16* __restrict__ Ch,
                        int N, int K, int mode)
{
    gemm1_core(Ah, Wh, bias, C, Ch, N, K, mode,
               blockIdx.y * 128, blockIdx.x * 128);
}

struct QKVArgs {
    const bf16* Wh[3];
    const float* bias[3];
    bf16* Ch[3];
};
__global__ __launch_bounds__(256)
void qkv_gemm_kernel(const bf16* __restrict__ Ah, QKVArgs a)
{
    int z = blockIdx.z;
    gemm1_core(Ah, a.Wh[z], a.bias[z], nullptr, a.Ch[z],
               Dsz, Dsz, 8, blockIdx.y * 128, blockIdx.x * 128);
}

// ---------------- FF GEMM: BM=128, BN=256, BK=32, 4-stage, TERMS in {2,3} ------
#define WP2 264             // 256 + 8 pad
#define FSA (128*AP2*2)     // 10240
#define FSW (32*WP2*2)      // 16896
#define FSMEM3 (4*(2*FSA + 2*FSW))   // 217088
#define FSMEM2 (4*(2*FSA + FSW))     // 149504

template<int TERMS>
__device__ __forceinline__
void ff_core(const bf16* __restrict__ Ah, const bf16* __restrict__ Al,
             const bf16* __restrict__ Wh, const bf16* __restrict__ Wl,
             const float* __restrict__ bias, float* __restrict__ C,
             bf16* __restrict__ Ch, bf16* __restrict__ Cl,
             int N, int K, int mode, int row0, int col0)
{
    extern __shared__ __align__(16) char gdsm[];
    const uint32_t aAh = (uint32_t)__cvta_generic_to_shared(gdsm);
    const uint32_t aAl = aAh + 4*FSA;
    const uint32_t aWh = aAl + 4*FSA;
    const uint32_t aWl = aWh + 4*FSW;   // TERMS==3 only

    const int tid = threadIdx.x;

    const int arow = tid >> 1;
    const int ach0 = (tid & 1) * 2;
    const char* pAh = (const char*)(Ah + (size_t)(row0 + arow) * K);
    const char* pAl = (const char*)(Al + (size_t)(row0 + arow) * K);
    const uint32_t dA0 = (uint32_t)((arow*AP2 + ach0*8) * 2);

    const int wk0 = tid >> 5;
    const int wcol = (tid & 31) * 8;
    const char* pWh = (const char*)(Wh + (size_t)wk0 * N + col0 + wcol);
    const char* pWl = (TERMS == 3) ? (const char*)(Wl + (size_t)wk0 * N + col0 + wcol) : nullptr;
    const uint32_t dW0 = (uint32_t)((wk0*WP2 + wcol) * 2);

    float acc[4][8][4];
    #pragma unroll
    for (int i = 0; i < 4; i++)
        #pragma unroll
        for (int j = 0; j < 8; j++)
            #pragma unroll
            for (int t = 0; t < 4; t++) acc[i][j][t] = 0.0f;

    const int wid = tid >> 5, lane = tid & 31;
    const int wm = wid & 1;
    const int wn = wid >> 1;
    const int lrow = lane & 15, lk = (lane >> 4) * 8;
    const uint32_t offA0 = (uint32_t)(((wm*64 + lrow) * AP2 + lk) * 2);
    const uint32_t offB0 = (uint32_t)(((lane & 15) * WP2 + wn*64 + (lane>>4)*8) * 2);

    const int nit = K / 32;

    auto load_stage = [&](int st, int it2) {
        size_t ka = (size_t)it2 * 32 * 2;
        size_t kw = (size_t)it2 * 32 * (size_t)N * 2;
        uint32_t sa = aAh + (uint32_t)(st*FSA);
        uint32_t sl = aAl + (uint32_t)(st*FSA);
        #pragma unroll
        for (int j = 0; j < 2; j++) {
            uint32_t so = dA0 + (uint32_t)(j*16);
            size_t  go = ka + (size_t)(ach0 + j) * 16;
            cp16(sa + so, pAh + go);
            cp16(sl + so, pAl + go);
        }
        uint32_t swh = aWh + (uint32_t)(st*FSW);
        #pragma unroll
        for (int j = 0; j < 4; j++) {
            uint32_t so = dW0 + (uint32_t)(j*8*WP2*2);
            size_t  go = kw + (size_t)(j*8) * N * 2;
            cp16(swh + so, pWh + go);
        }
        if (TERMS == 3) {
            uint32_t swl = aWl + (uint32_t)(st*FSW);
            #pragma unroll
            for (int j = 0; j < 4; j++) {
                uint32_t so = dW0 + (uint32_t)(j*8*WP2*2);
                size_t  go = kw + (size_t)(j*8) * N * 2;
                cp16(swl + so, pWl + go);
            }
        }
        cp_commit();
    };

    load_stage(0, 0);
    load_stage(1, 1);
    load_stage(2, 2);

    for (int it = 0; it < nit; ++it) {
        int rem = nit - 1 - it;
        if (rem >= 2) cp_wait2();
        else if (rem == 1) cp_wait1();
        else cp_wait0();
        __syncthreads();
        if (it + 3 < nit)
            load_stage((it + 3) & 3, it + 3);
        const uint32_t s = (uint32_t)(it & 3);

        #pragma unroll
        for (int kh = 0; kh < 2; kh++) {
            const uint32_t kaoff = (uint32_t)(kh * 16 * 2);
            const uint32_t kwoff = (uint32_t)(kh * 16 * WP2 * 2);

            uint32_t afh[4][4];
            #pragma unroll
            for (int mi = 0; mi < 4; mi++)
                ldsm4(afh[mi], aAh + s*FSA + offA0 + kaoff + (uint32_t)(mi*16*AP2*2));
            uint32_t afl[4][4];
            #pragma unroll
            for (int mi = 0; mi < 4; mi++)
                ldsm4(afl[mi], aAl + s*FSA + offA0 + kaoff + (uint32_t)(mi*16*AP2*2));

            uint32_t bfr[8][2];
            #pragma unroll
            for (int ng = 0; ng < 4; ng++)
                ldsm4t(bfr[2*ng][0], bfr[2*ng][1], bfr[2*ng+1][0], bfr[2*ng+1][1],
                       aWh + s*FSW + offB0 + kwoff + (uint32_t)(ng*16*2));

            #pragma unroll
            for (int mi = 0; mi < 4; mi++)
                #pragma unroll
                for (int ni = 0; ni < 8; ni++) {
                    mma16816(acc[mi][ni], afh[mi], bfr[ni][0], bfr[ni][1]);
                    mma16816(acc[mi][ni], afl[mi], bfr[ni][0], bfr[ni][1]);
                }

            if (TERMS == 3) {
                #pragma unroll
                for (int ng = 0; ng < 4; ng++)
                    ldsm4t(bfr[2*ng][0], bfr[2*ng][1], bfr[2*ng+1][0], bfr[2*ng+1][1],
                           aWl + s*FSW + offB0 + kwoff + (uint32_t)(ng*16*2));
                #pragma unroll
                for (int mi = 0; mi < 4; mi++)
                    #pragma unroll
                    for (int ni = 0; ni < 8; ni++)
                        mma16816(acc[mi][ni], afh[mi], bfr[ni][0], bfr[ni][1]);
            }
        }
    }

    #pragma unroll
    for (int mi = 0; mi < 4; mi++) {
        #pragma unroll
        for (int ni = 0; ni < 8; ni++) {
            int c = col0 + wn*64 + ni*8 + (lane & 3)*2;
            float bx = bias[c], by = bias[c + 1];
            #pragma unroll
            for (int rh = 0; rh < 2; rh++) {
                size_t r = (size_t)(row0 + wm*64 + mi*16 + (lane >> 2) + rh*8);
                float v0 = acc[mi][ni][2*rh]     + bx;
                float v1 = acc[mi][ni][2*rh + 1] + by;
                if (mode & 1) {
                    v0 = 0.5f * v0 * (1.0f + erff(v0 * 0.70710678118654752f));
                    v1 = 0.5f * v1 * (1.0f + erff(v1 * 0.70710678118654752f));
                }
                if (mode & 2) {
                    float2 o; o.x = v0; o.y = v1;
                    *(float2*)&C[r * N + c] = o;
                }
                if (mode & 4) {
                    uint32_t hp, lp;
                    pack_pair(v0, v1, hp, lp);
                    *(uint32_t*)&Ch[r * N + c] = hp;
                    *(uint32_t*)&Cl[r * N + c] = lp;
                }
            }
        }
    }
}

__global__ __launch_bounds__(256, 1)
void ff3_gemm_kernel(const bf16* __restrict__ Ah, const bf16* __restrict__ Al,
                     const bf16* __restrict__ Wh, const bf16* __restrict__ Wl,
                     const float* __restrict__ bias,
                     bf16* __restrict__ Ch, bf16* __restrict__ Cl,
                     int N, int K, int mode)
{
    ff_core<3>(Ah, Al, Wh, Wl, bias, nullptr, Ch, Cl, N, K, mode,
               blockIdx.y * 128, blockIdx.x * 256);
}

__global__ __launch_bounds__(256, 1)
void ff2_gemm_kernel(const bf16* __restrict__ Ah, const bf16* __restrict__ Al,
                     const bf16* __restrict__ Wh,
                     const float* __restrict__ bias, float* __restrict__ C,
                     int N, int K, int mode)
{
    ff_core<2>(Ah, Al, Wh, nullptr, bias, C, nullptr, nullptr, N, K, mode,
               blockIdx.y * 128, blockIdx.x * 256);
}

// ---------------- sigmoid gate ----------------------
__global__ __launch_bounds__(256)
void gate_kernel(const float* __restrict__ x, const float* __restrict__ wg,
                 const float* __restrict__ bg, float* __restrict__ gate)
{
    __shared__ float wgs[Dsz][8];
    int hg = blockIdx.y;
    int tid = threadIdx.x;
    for (int idx = tid; idx < Dsz*8; idx += 256)
        wgs[idx >> 3][idx & 7] = wg[(idx >> 3) * Hsz + hg*8 + (idx & 7)];
    __syncthreads();

    int h = tid & 7, r = tid >> 3;
    int m = blockIdx.x * 32 + r;
    const float4* xr = (const float4*)(x + (size_t)m * Dsz);
    float s = 0.0f;
    #pragma unroll 4
    for (int d4 = 0; d4 < Dsz/4; d4++) {
        float4 xv = xr[d4];
        s = fmaf(xv.x, wgs[d4*4 + 0][h], s);
        s = fmaf(xv.y, wgs[d4*4 + 1][h], s);
        s = fmaf(xv.z, wgs[d4*4 + 2][h], s);
        s = fmaf(xv.w, wgs[d4*4 + 3][h], s);
    }
    s += bg[hg*8 + h];
    gate[(size_t)m * Hsz + hg*8 + h] = 1.0f / (1.0f + __expf(-s));
}

// ---------------- tensor-core flash attention (bf16, 128-q tile, 8 warps) ------
#define FPAD 72
#define KV_STRIDE (64*FPAD)
#define Q_STRIDE  (128*FPAD)
#define KV_STAGE  (2*KV_STRIDE)
#define FLASH_SMEM (Q_STRIDE*2 + 2*KV_STAGE*2 + 2*64*4)

__global__ __launch_bounds__(256, 2)
void flash_tc_kernel(const bf16* __restrict__ Qh,
                     const bf16* __restrict__ Kh,
                     const bf16* __restrict__ Vh,
                     const float* __restrict__ gate, const int* __restrict__ mask,
                     bf16* __restrict__ Ch)
{
    extern __shared__ __align__(16) char dynsmem[];
    const uint32_t qbase = (uint32_t)__cvta_generic_to_shared(dynsmem);
    const uint32_t kvbase = qbase + Q_STRIDE*2;
    const uint32_t mbase = kvbase + 2*KV_STAGE*2;
    int* smsk = (int*)(dynsmem + (size_t)Q_STRIDE*2 + (size_t)2*KV_STAGE*2);

    const int tid = threadIdx.x, lane = tid & 31, warp = tid >> 5;
    const int qt = blockIdx.x, h = blockIdx.y, b = blockIdx.z;
    const size_t rowbase = (size_t)b * Ssz;
    const size_t hoff = (size_t)h * DKsz;

    {
        int r = tid >> 1;
        size_t gq = (rowbase + qt*128 + r) * Dsz + hoff;
        #pragma unroll
        for (int j = 0; j < 4; j++) {
            int c8 = (tid & 1)*4 + j;
            uint32_t dof = (uint32_t)((r*FPAD + c8*8)*2);
            cp16(qbase + dof, Qh + gq + c8*8);
        }
        cp_commit(); cp_wait0();
    }
    __syncthreads();

    uint32_t qfh[4][4];
    {
        uint32_t arow = (uint32_t)((warp*16 + (lane&15))*FPAD*2);
        #pragma unroll
        for (int ks = 0; ks < 4; ks++) {
            uint32_t acol = (uint32_t)((16*ks + (lane>>4)*8)*2);
            ldsm4(qfh[ks], qbase + arow + acol);
        }
    }
    __syncthreads();

    float oacc[8][4];
    #pragma unroll
    for (int i = 0; i < 8; i++)
        #pragma unroll
        for (int j = 0; j < 4; j++) oacc[i][j] = 0.0f;
    float m0 = -1e30f, m1 = -1e30f, l0 = 0.0f, l1 = 0.0f;

    const int r_ld = tid >> 2;
    const int cbase = (tid & 3)*2;

    {
        size_t g = (rowbase + r_ld) * Dsz + hoff;
        #pragma unroll
        for (int j = 0; j < 2; j++) {
            int c8 = cbase + j;
            uint32_t dof = (uint32_t)((r_ld*FPAD + c8*8)*2);
            cp16(kvbase + dof, Kh + g + c8*8);
            cp16(kvbase + KV_STRIDE*2 + dof, Vh + g + c8*8);
        }
        if (tid < 16) cp16(mbase + tid*16, mask + rowbase + tid*4);
        cp_commit();
    }

    const int col0 = 2*(lane & 3);

    for (int kt = 0; kt < Ssz/64; kt++) {
        cp_wait0();
        __syncthreads();
        if (kt + 1 < Ssz/64) {
            int st = (kt + 1) & 1;
            size_t g = (rowbase + (kt+1)*64 + r_ld) * Dsz + hoff;
            uint32_t sb = kvbase + (uint32_t)(st*KV_STAGE*2);
            #pragma unroll
            for (int j = 0; j < 2; j++) {
                int c8 = cbase + j;
                uint32_t dof = (uint32_t)((r_ld*FPAD + c8*8)*2);
                cp16(sb + dof, Kh + g + c8*8);
                cp16(sb + KV_STRIDE*2 + dof, Vh + g + c8*8);
            }
            if (tid < 16) cp16(mbase + st*256 + tid*16, mask + rowbase + (kt+1)*64 + tid*4);
            cp_commit();
        }
        const int st = kt & 1;
        const uint32_t kb = kvbase + (uint32_t)(st*KV_STAGE*2);

        float sc[8][4];
        #pragma unroll
        for (int i = 0; i < 8; i++)
            #pragma unroll
            for (int j = 0; j < 4; j++) sc[i][j] = 0.0f;

        const uint32_t brow = (uint32_t)(((lane&7) + ((lane>>1)&8)) * FPAD * 2);
        const uint32_t bcol = (uint32_t)((lane & 8) * 2);
        #pragma unroll
        for (int ng = 0; ng < 4; ng++) {
            #pragma unroll
            for (int ks = 0; ks < 4; ks++) {
                uint32_t ba = kb + brow + (uint32_t)(16*ng*FPAD*2) + bcol + (uint32_t)(16*ks*2);
                uint32_t bh4[4];
                ldsm4(bh4, ba);
                mma16816(sc[2*ng],   qfh[ks], bh4[0], bh4[1]);
                mma16816(sc[2*ng+1], qfh[ks], bh4[2], bh4[3]);
            }
        }

        const int* mk = smsk + st*64;
        float mx0 = -1e30f, mx1 = -1e30f;
        #pragma unroll
        for (int ni = 0; ni < 8; ni++) {
            int c = 8*ni + col0;
            bool z0 = (mk[c] == 0), z1 = (mk[c+1] == 0);
            sc[ni][0] = z0 ? -1e9f : sc[ni][0]*0.125f;
            sc[ni][1] = z1 ? -1e9f : sc[ni][1]*0.125f;
            sc[ni][2] = z0 ? -1e9f : sc[ni][2]*0.125f;
            sc[ni][3] = z1 ? -1e9f : sc[ni][3]*0.125f;
            mx0 = fmaxf(mx0, fmaxf(sc[ni][0], sc[ni][1]));
            mx1 = fmaxf(mx1, fmaxf(sc[ni][2], sc[ni][3]));
        }
        mx0 = fmaxf(mx0, __shfl_xor_sync(0xffffffffu, mx0, 1));
        mx0 = fmaxf(mx0, __shfl_xor_sync(0xffffffffu, mx0, 2));
        mx1 = fmaxf(mx1, __shfl_xor_sync(0xffffffffu, mx1, 1));
        mx1 = fmaxf(mx1, __shfl_xor_sync(0xffffffffu, mx1, 2));
        float mn0 = fmaxf(m0, mx0), mn1 = fmaxf(m1, mx1);
        float al0 = __expf(m0 - mn0), al1 = __expf(m1 - mn1);
        float rs0 = 0.0f, rs1 = 0.0f;
        #pragma unroll
        for (int ni = 0; ni < 8; ni++) {
            sc[ni][0] = __expf(sc[ni][0] - mn0);
            sc[ni][1] = __expf(sc[ni][1] - mn0);
            sc[ni][2] = __expf(sc[ni][2] - mn1);
            sc[ni][3] = __expf(sc[ni][3] - mn1);
            rs0 += sc[ni][0] + sc[ni][1];
            rs1 += sc[ni][2] + sc[ni][3];
        }
        rs0 += __shfl_xor_sync(0xffffffffu, rs0, 1);
        rs0 += __shfl_xor_sync(0xffffffffu, rs0, 2);
        rs1 += __shfl_xor_sync(0xffffffffu, rs1, 1);
        rs1 += __shfl_xor_sync(0xffffffffu, rs1, 2);
        l0 = l0*al0 + rs0; l1 = l1*al1 + rs1;
        m0 = mn0; m1 = mn1;
        #pragma unroll
        for (int ni = 0; ni < 8; ni++) {
            oacc[ni][0] *= al0; oacc[ni][1] *= al0;
            oacc[ni][2] *= al1; oacc[ni][3] *= al1;
        }

        const uint32_t vrow0 = (uint32_t)((lane&15)*FPAD*2);
        const uint32_t vcol0 = (uint32_t)(((lane>>4)*8)*2);
        #pragma unroll
        for (int ki = 0; ki < 4; ki++) {
            uint32_t ph[4];
            ph[0] = pack_hi(sc[2*ki][0],   sc[2*ki][1]);
            ph[1] = pack_hi(sc[2*ki][2],   sc[2*ki][3]);
            ph[2] = pack_hi(sc[2*ki+1][0], sc[2*ki+1][1]);
            ph[3] = pack_hi(sc[2*ki+1][2], sc[2*ki+1][3]);
            uint32_t va0 = kb + KV_STRIDE*2 + vrow0 + (uint32_t)(16*ki*FPAD*2) + vcol0;
            #pragma unroll
            for (int ngd = 0; ngd < 4; ngd++) {
                uint32_t vh4[4];
                ldsm4t(vh4[0], vh4[1], vh4[2], vh4[3], va0 + (uint32_t)(16*ngd*2));
                mma16816(oacc[2*ngd],   ph, vh4[0], vh4[1]);
                mma16816(oacc[2*ngd+1], ph, vh4[2], vh4[3]);
            }
        }
    }

    int q0 = qt*128 + warp*16 + (lane >> 2);
    float f0 = gate[(rowbase + q0)*Hsz + h] / l0;
    float f1 = gate[(rowbase + q0 + 8)*Hsz + h] / l1;
    #pragma unroll
    for (int ni = 0; ni < 8; ni++) {
        size_t o0 = (rowbase + q0) * Dsz + hoff + 8*ni + col0;
        size_t o1 = o0 + (size_t)8 * Dsz;
        *(uint32_t*)&Ch[o0] = pack_hi(oacc[ni][0]*f0, oacc[ni][1]*f0);
        *(uint32_t*)&Ch[o1] = pack_hi(oacc[ni][2]*f1, oacc[ni][3]*f1);
    }
}

// ---------------- fused add+LN: one float4 per thread (Dsz = 256*4) -----------
__global__ __launch_bounds__(256)
void add_ln_kernel(const float* __restrict__ a, const float* __restrict__ bsrc,
                   const float* __restrict__ g, const float* __restrict__ beta,
                   float* __restrict__ out, bf16* __restrict__ oh, bf16* __restrict__ ol)
{
    int row = blockIdx.x;
    int tid = threadIdx.x;
    __shared__ float rsum[8], rsq[8];

    size_t base = (size_t)row * Dsz;
    float4 va = ((const float4*)(a + base))[tid];
    float4 vb = ((const float4*)(bsrc + base))[tid];
    float4 v;
    v.x = va.x + vb.x; v.y = va.y + vb.y; v.z = va.z + vb.z; v.w = va.w + vb.w;
    float ls = v.x + v.y + v.z + v.w;
    float lq = v.x*v.x + v.y*v.y + v.z*v.z + v.w*v.w;

    int warp = tid >> 5, lane = tid & 31;
    for (int off = 16; off; off >>= 1) {
        ls += __shfl_xor_sync(0xffffffffu, ls, off);
        lq += __shfl_xor_sync(0xffffffffu, lq, off);
    }
    if (lane == 0) { rsum[warp] = ls; rsq[warp] = lq; }
    __syncthreads();
    float ts = 0.0f, tq = 0.0f;
    #pragma unroll
    for (int w = 0; w < 8; w++) { ts += rsum[w]; tq += rsq[w]; }
    float mean = ts * (1.0f / Dsz);
    float var  = tq * (1.0f / Dsz) - mean * mean;
    float rstd = rsqrtf(var + 1e-5f);

    float4 gv = ((const float4*)g)[tid];
    float4 bv = ((const float4*)beta)[tid];
    float4 o;
    o.x = (v.x - mean) * rstd * gv.x + bv.x;
    o.y = (v.y - mean) * rstd * gv.y + bv.y;
    o.z = (v.z - mean) * rstd * gv.z + bv.z;
    o.w = (v.w - mean) * rstd * gv.w + bv.w;
    ((float4*)(out + base))[tid] = o;
    if (oh) {
        uint32_t h0, l0, h1, l1;
        pack_pair(o.x, o.y, h0, l0);
        pack_pair(o.z, o.w, h1, l1);
        uint32_t* hp = (uint32_t*)(oh + base);
        uint32_t* lp = (uint32_t*)(ol + base);
        hp[2*tid] = h0; hp[2*tid+1] = h1;
        lp[2*tid] = l0; lp[2*tid+1] = l1;
    }
}

// ---------------- launch ----------------
extern "C" void kernel_launch(void* const* d_in, const int* in_sizes, int n_in,
                              void* d_out, int out_size)
{
    const float* x     = (const float*)d_in[0];
    const float* w_q   = (const float*)d_in[1];
    const float* b_q   = (const float*)d_in[2];
    const float* w_k   = (const float*)d_in[3];
    const float* b_k   = (const float*)d_in[4];
    const float* w_v   = (const float*)d_in[5];
    const float* b_v   = (const float*)d_in[6];
    const float* w_o   = (const float*)d_in[7];
    const float* b_o   = (const float*)d_in[8];
    const float* w_g   = (const float*)d_in[9];
    const float* b_g   = (const float*)d_in[10];
    const float* w1    = (const float*)d_in[11];
    const float* b1    = (const float*)d_in[12];
    const float* w2    = (const float*)d_in[13];
    const float* b2    = (const float*)d_in[14];
    const float* g1    = (const float*)d_in[15];
    const float* beta1 = (const float*)d_in[16];
    const float* g2    = (const float*)d_in[17];
    const float* beta2 = (const float*)d_in[18];
    const int*   mask  = (const int*)  d_in[19];
    float* out = (float*)d_out;

    float *tmp, *x1, *gate;
    cudaGetSymbolAddress((void**)&tmp,  g_tmp);
    cudaGetSymbolAddress((void**)&x1,   g_x1);
    cudaGetSymbolAddress((void**)&gate, g_gate);

    bf16 *xh,*xl,*qh,*kh,*vh,*ctxh,*x1h,*x1l,*ffh,*ffl;
    bf16 *wqh,*wkh,*wvh,*woh,*w1h,*w1l,*w2h;
    cudaGetSymbolAddress((void**)&xh,  g_xh);   cudaGetSymbolAddress((void**)&xl,  g_xl);
    cudaGetSymbolAddress((void**)&qh,  g_qh);
    cudaGetSymbolAddress((void**)&kh,  g_kh);
    cudaGetSymbolAddress((void**)&vh,  g_vh);
    cudaGetSymbolAddress((void**)&ctxh,g_ctxh);
    cudaGetSymbolAddress((void**)&x1h, g_x1h);  cudaGetSymbolAddress((void**)&x1l, g_x1l);
    cudaGetSymbolAddress((void**)&ffh, g_ffh);  cudaGetSymbolAddress((void**)&ffl, g_ffl);
    cudaGetSymbolAddress((void**)&wqh, g_wqh);
    cudaGetSymbolAddress((void**)&wkh, g_wkh);
    cudaGetSymbolAddress((void**)&wvh, g_wvh);
    cudaGetSymbolAddress((void**)&woh, g_woh);
    cudaGetSymbolAddress((void**)&w1h, g_w1h);  cudaGetSymbolAddress((void**)&w1l, g_w1l);
    cudaGetSymbolAddress((void**)&w2h, g_w2h);

    cudaFuncSetAttribute(flash_tc_kernel,
                         cudaFuncAttributeMaxDynamicSharedMemorySize, FLASH_SMEM);
    cudaFuncSetAttribute(gemm_bf16x1_kernel,
                         cudaFuncAttributeMaxDynamicSharedMemorySize, GSMEM1);
    cudaFuncSetAttribute(qkv_gemm_kernel,
                         cudaFuncAttributeMaxDynamicSharedMemorySize, GSMEM1);
    cudaFuncSetAttribute(ff3_gemm_kernel,
                         cudaFuncAttributeMaxDynamicSharedMemorySize, FSMEM3);
    cudaFuncSetAttribute(ff2_gemm_kernel,
                         cudaFuncAttributeMaxDynamicSharedMemorySize, FSMEM2);

    // 0: split x (hi+lo)
    split_x_kernel<<<Msz*Dsz/(4*512), 256>>>(x, xh, xl);

    // 1: split weights (w1 hi+lo; others hi only)
    SplitWArgs sw;
    sw.src[0] = w_q; sw.hi[0] = wqh; sw.lo[0] = nullptr;
    sw.src[1] = w_k; sw.hi[1] = wkh; sw.lo[1] = nullptr;
    sw.src[2] = w_v; sw.hi[2] = wvh; sw.lo[2] = nullptr;
    sw.src[3] = w_o; sw.hi[3] = woh; sw.lo[3] = nullptr;
    sw.src[4] = w1;  sw.hi[4] = w1h; sw.lo[4] = w1l;
    sw.src[5] = w2;  sw.hi[5] = w2h; sw.lo[5] = nullptr;
    split_w_kernel<<<6144, 256>>>(sw);

    // 2: gate
    gate_kernel<<<dim3(Msz/32, 2), 256>>>(x, w_g, b_g, gate);

    // 3: merged QKV GEMM (1-term, BK=32) <- profiled slot
    QKVArgs qa;
    qa.Wh[0] = wqh; qa.bias[0] = b_q; qa.Ch[0] = qh;
    qa.Wh[1] = wkh; qa.bias[1] = b_k; qa.Ch[1] = kh;
    qa.Wh[2] = wvh; qa.bias[2] = b_v; qa.Ch[2] = vh;
    qkv_gemm_kernel<<<dim3(Dsz/128, Msz/128, 3), 256, GSMEM1>>>(xh, qa);

    // 4: flash attention
    flash_tc_kernel<<<dim3(Ssz/128, Hsz, Bsz), 256, FLASH_SMEM>>>(
        qh, kh, vh, gate, mask, ctxh);

    // 5: O-proj (1-term, BK=32)
    gemm_bf16x1_kernel<<<dim3(Dsz/128, Msz/128), 256, GSMEM1>>>(
        ctxh, woh, b_o, tmp, nullptr, Dsz, Dsz, 2);
    // 6: LN1
    add_ln_kernel<<<Msz, 256>>>(x, tmp, g1, beta1, x1, x1h, x1l);
    // 7: FF1 (3-term, BK=32, 4-stage, GELU)
    ff3_gemm_kernel<<<dim3(DFFsz/256, Msz/128), 256, FSMEM3>>>(
        x1h, x1l, w1h, w1l, b1, ffh, ffl, DFFsz, Dsz, 5);
    // 8: FF2 (2-term, BK=32, 4-stage)
    ff2_gemm_kernel<<<dim3(Dsz/256, Msz/128), 256, FSMEM2>>>(
        ffh, ffl, w2h, b2, tmp, Dsz, DFFsz, 2);
    // 9: LN2
    add_ln_kernel<<<Msz, 256>>>(x1, tmp, g2, beta2, out, nullptr, nullptr);
}